// round 7
// baseline (speedup 1.0000x reference)
#include <cuda_runtime.h>
#include <cuda_fp16.h>
#include <cstdint>

#define B_  16
#define T_  2048
#define E_  512
#define H_  4
#define C_  3
#define NT  (B_ * T_)   // 32768 tokens

// ---------------------------------------------------------------------------
// Scratch (static device globals — allowed)
// ---------------------------------------------------------------------------
__device__ __half g_v[(size_t)NT * E_];    // 32 MB, fp16(v)
__device__ __half g_w[(size_t)E_ * E_];    // 512 KB, fp16(W)

__device__ __forceinline__ uint32_t smem_to_u32(const void* p) {
    uint32_t a;
    asm("{ .reg .u64 t; cvta.to.shared.u64 t, %1; cvt.u32.u64 %0, t; }" : "=r"(a) : "l"(p));
    return a;
}
__device__ __forceinline__ void cp16(uint32_t dst, const void* src) {
    asm volatile("cp.async.cg.shared.global [%0], [%1], 16;" :: "r"(dst), "l"(src));
}
__device__ __forceinline__ void ldm_x4(uint32_t* r, uint32_t addr) {
    asm volatile("ldmatrix.sync.aligned.m8n8.x4.shared.b16 {%0,%1,%2,%3}, [%4];"
                 : "=r"(r[0]), "=r"(r[1]), "=r"(r[2]), "=r"(r[3]) : "r"(addr));
}
__device__ __forceinline__ void mma_fp16(float* d, const uint32_t* a, const uint32_t* b) {
    asm volatile(
        "mma.sync.aligned.m16n8k16.row.col.f32.f16.f16.f32 "
        "{%0,%1,%2,%3}, {%4,%5,%6,%7}, {%8,%9}, {%0,%1,%2,%3};"
        : "+f"(d[0]), "+f"(d[1]), "+f"(d[2]), "+f"(d[3])
        : "r"(a[0]), "r"(a[1]), "r"(a[2]), "r"(a[3]), "r"(b[0]), "r"(b[1]));
}

// ---------------------------------------------------------------------------
// Kernel A: embed gather + windowed positional attention -> v (fp16)
// ---------------------------------------------------------------------------
__global__ __launch_bounds__(256, 2) void attn_kernel(const int* __restrict__ tokens,
                                                      const float* __restrict__ table,
                                                      const float* __restrict__ pos) {
    __shared__ float pos_s[H_ * E_ * C_];  // pos[h][e][c]
    int tid = threadIdx.x;
    for (int i = tid; i < H_ * E_ * C_; i += 256) pos_s[i] = pos[i];
    __syncthreads();

    int warp = tid >> 5, lane = tid & 31;
    int base = blockIdx.x * 32 + warp * 4;
    int t0 = base & (T_ - 1);

    float x0[16], x1[16], x2[16];
    if (t0 >= 2) {
        const float* rp = table + (size_t)tokens[base - 2] * E_;
        #pragma unroll
        for (int j = 0; j < 16; ++j) x0[j] = rp[lane + j * 32];
    } else {
        #pragma unroll
        for (int j = 0; j < 16; ++j) x0[j] = 0.0f;
    }
    if (t0 >= 1) {
        const float* rp = table + (size_t)tokens[base - 1] * E_;
        #pragma unroll
        for (int j = 0; j < 16; ++j) x1[j] = rp[lane + j * 32];
    } else {
        #pragma unroll
        for (int j = 0; j < 16; ++j) x1[j] = 0.0f;
    }

    #pragma unroll 1
    for (int it = 0; it < 4; ++it) {
        int g = base + it;
        {
            const float* rp = table + (size_t)tokens[g] * E_;
            #pragma unroll
            for (int j = 0; j < 16; ++j) x2[j] = rp[lane + j * 32];
        }

        float s[12];
        #pragma unroll
        for (int i = 0; i < 12; ++i) s[i] = 0.0f;
        #pragma unroll
        for (int j = 0; j < 16; ++j) {
            int e = lane + j * 32;
            #pragma unroll
            for (int h = 0; h < 4; ++h) {
                const float* pp = pos_s + h * (E_ * C_) + e * C_;
                s[h * 3 + 0] = fmaf(x0[j], pp[0], s[h * 3 + 0]);
                s[h * 3 + 1] = fmaf(x1[j], pp[1], s[h * 3 + 1]);
                s[h * 3 + 2] = fmaf(x2[j], pp[2], s[h * 3 + 2]);
            }
        }
        #pragma unroll
        for (int off = 16; off > 0; off >>= 1) {
            #pragma unroll
            for (int i = 0; i < 12; ++i)
                s[i] += __shfl_xor_sync(0xffffffffu, s[i], off);
        }
        float c0 = (s[0] + s[3] + s[6] + s[9])  * (1.0f / 12.0f);
        float c1 = (s[1] + s[4] + s[7] + s[10]) * (1.0f / 12.0f);
        float c2 = (s[2] + s[5] + s[8] + s[11]) * (1.0f / 12.0f);

        __half* pv = g_v + (size_t)g * E_;
        #pragma unroll
        for (int j = 0; j < 16; ++j) {
            float v = c0 * x0[j] + c1 * x1[j] + c2 * x2[j];
            pv[lane + j * 32] = __float2half_rn(v);
        }
        #pragma unroll
        for (int j = 0; j < 16; ++j) { x0[j] = x1[j]; x1[j] = x2[j]; }
    }
}

// ---------------------------------------------------------------------------
// Kernel W: convert ffn_w to fp16
// ---------------------------------------------------------------------------
__global__ __launch_bounds__(256) void wconv_kernel(const float* __restrict__ W) {
    int i = blockIdx.x * 256 + threadIdx.x;
    g_w[i] = __float2half_rn(W[i]);
}

// ---------------------------------------------------------------------------
// Kernel B: fused HMMA fp16 GEMM + bias + LayerNorm + swish.
// CTA tile 64 x 512 (full N), 512 threads = 16 warps (2m x 8n), warp 32x64.
// 64 accum regs/thread. KBLK=32, 4-stage cp.async.
// ---------------------------------------------------------------------------
#define KBLK   32
#define PITCH  80
#define SMA_SZ (64 * PITCH)              // 5120
#define SMB_SZ (512 * PITCH)             // 40960
#define STAGE  (SMA_SZ + SMB_SZ)         // 46080
#define NSTG   4
#define SM_GEMM (NSTG * STAGE)           // 184320 bytes dynamic

__global__ __launch_bounds__(512, 1) void gemm_ln_kernel(const float* __restrict__ bias,
                                                         const float* __restrict__ gamma,
                                                         const float* __restrict__ beta,
                                                         float* __restrict__ out) {
    extern __shared__ char smem[];
    __shared__ float bias_s[E_], gam_s[E_], bet_s[E_];
    __shared__ float2 part_s[64][8];     // (sum, sumsq) per row per n-warp

    const uint32_t sb = smem_to_u32(smem);
    const int tid  = threadIdx.x;
    const int wid  = tid >> 5, lane = tid & 31;
    const int wm   = wid >> 3;           // 0..1
    const int wn   = wid & 7;            // 0..7
    const int m0   = blockIdx.x * 64;

    for (int i = tid; i < E_; i += 512) {
        bias_s[i] = bias[i]; gam_s[i] = gamma[i]; bet_s[i] = beta[i];
    }

    const char* va = (const char*)g_v;
    const char* wb = (const char*)g_w;

    auto issue_stage = [&](int kb) {
        const uint32_t st = sb + (kb & (NSTG - 1)) * STAGE;
        const int k0 = kb * KBLK;
        if (tid < 256) {   // A: 64 rows x 4 chunks of 16B
            int r = tid >> 2, c = tid & 3;
            uint32_t so = r * PITCH + c * 16;
            size_t ga = ((size_t)(m0 + r) * E_ + k0 + c * 8) * 2;
            cp16(st + so, va + ga);
        }
        #pragma unroll
        for (int it = 0; it < 4; ++it) {   // B: 512 rows x 4 chunks
            int i = tid + it * 512;
            int r = i >> 2, c = i & 3;
            uint32_t so = r * PITCH + c * 16;
            size_t gb = ((size_t)r * E_ + k0 + c * 8) * 2;
            cp16(st + SMA_SZ + so, wb + gb);
        }
        asm volatile("cp.async.commit_group;" ::: "memory");
    };

    float d[2][8][4];
    #pragma unroll
    for (int i = 0; i < 2; ++i)
        #pragma unroll
        for (int j = 0; j < 8; ++j)
            #pragma unroll
            for (int q = 0; q < 4; ++q) d[i][j][q] = 0.0f;

    const int a_row = (lane & 7) + ((lane >> 3) & 1) * 8;
    const int a_k8  = (lane >> 4);
    const int b_row = (lane & 7) + ((lane >> 4) & 1) * 8;
    const int b_k8  = (lane >> 3) & 1;

    issue_stage(0);
    issue_stage(1);
    issue_stage(2);

    const int NKB = E_ / KBLK;   // 16
    for (int kb = 0; kb < NKB; ++kb) {
        if (kb < NKB - 2)
            asm volatile("cp.async.wait_group 2;" ::: "memory");
        else if (kb == NKB - 2)
            asm volatile("cp.async.wait_group 1;" ::: "memory");
        else
            asm volatile("cp.async.wait_group 0;" ::: "memory");
        __syncthreads();

        const uint32_t st = sb + (kb & (NSTG - 1)) * STAGE;
        const uint32_t aT = st;
        const uint32_t bT = st + SMA_SZ;

        #pragma unroll
        for (int kk = 0; kk < 2; ++kk) {
            uint32_t a[2][4];
            #pragma unroll
            for (int mi = 0; mi < 2; ++mi) {
                uint32_t off = (uint32_t)(wm * 32 + mi * 16 + a_row) * PITCH
                             + kk * 32 + a_k8 * 16;
                ldm_x4(a[mi], aT + off);
            }
            #pragma unroll
            for (int ni = 0; ni < 4; ++ni) {
                uint32_t off = (uint32_t)(wn * 64 + ni * 16 + b_row) * PITCH
                             + kk * 32 + b_k8 * 16;
                uint32_t bq[4];
                ldm_x4(bq, bT + off);
                #pragma unroll
                for (int mi = 0; mi < 2; ++mi) {
                    mma_fp16(d[mi][ni * 2 + 0], a[mi], bq + 0);
                    mma_fp16(d[mi][ni * 2 + 1], a[mi], bq + 2);
                }
            }
        }
        __syncthreads();
        if (kb + 3 < NKB) issue_stage(kb + 3);
    }

    // ---- Fused epilogue: bias + LayerNorm + swish ----
    const int g = lane >> 2, t = lane & 3;

    float psum[2][2], psq[2][2];   // [mi][half]
    #pragma unroll
    for (int mi = 0; mi < 2; ++mi)
        #pragma unroll
        for (int h2 = 0; h2 < 2; ++h2) { psum[mi][h2] = 0.0f; psq[mi][h2] = 0.0f; }

    #pragma unroll
    for (int mi = 0; mi < 2; ++mi) {
        #pragma unroll
        for (int nj = 0; nj < 8; ++nj) {
            int col = wn * 64 + (nj >> 1) * 16 + (nj & 1) * 8 + t * 2;
            float b0 = bias_s[col], b1 = bias_s[col + 1];
            float* dd = d[mi][nj];
            dd[0] += b0; dd[1] += b1; dd[2] += b0; dd[3] += b1;
            psum[mi][0] += dd[0] + dd[1];
            psq[mi][0]  += dd[0] * dd[0] + dd[1] * dd[1];
            psum[mi][1] += dd[2] + dd[3];
            psq[mi][1]  += dd[2] * dd[2] + dd[3] * dd[3];
        }
    }
    // reduce across the 4 lanes of each quad (t dimension)
    #pragma unroll
    for (int off = 1; off <= 2; off <<= 1) {
        #pragma unroll
        for (int mi = 0; mi < 2; ++mi)
            #pragma unroll
            for (int h2 = 0; h2 < 2; ++h2) {
                psum[mi][h2] += __shfl_xor_sync(0xffffffffu, psum[mi][h2], off);
                psq[mi][h2]  += __shfl_xor_sync(0xffffffffu, psq[mi][h2],  off);
            }
    }
    if (t == 0) {
        #pragma unroll
        for (int mi = 0; mi < 2; ++mi) {
            part_s[wm * 32 + mi * 16 + g][wn]     = make_float2(psum[mi][0], psq[mi][0]);
            part_s[wm * 32 + mi * 16 + g + 8][wn] = make_float2(psum[mi][1], psq[mi][1]);
        }
    }
    __syncthreads();

    #pragma unroll
    for (int mi = 0; mi < 2; ++mi) {
        #pragma unroll
        for (int h2 = 0; h2 < 2; ++h2) {
            int rl = wm * 32 + mi * 16 + g + h2 * 8;
            float sum = 0.0f, sq = 0.0f;
            #pragma unroll
            for (int w = 0; w < 8; ++w) {
                float2 p = part_s[rl][w];
                sum += p.x; sq += p.y;
            }
            float mean = sum * (1.0f / E_);
            float var  = sq * (1.0f / E_) - mean * mean;
            float rstd = rsqrtf(var + 1e-5f);

            float* op = out + (size_t)(m0 + rl) * E_;
            #pragma unroll
            for (int nj = 0; nj < 8; ++nj) {
                int col = wn * 64 + (nj >> 1) * 16 + (nj & 1) * 8 + t * 2;
                const float* dd = d[mi][nj];
                float y0 = dd[h2 * 2 + 0], y1 = dd[h2 * 2 + 1];
                float o0 = (y0 - mean) * rstd * gam_s[col]     + bet_s[col];
                float o1 = (y1 - mean) * rstd * gam_s[col + 1] + bet_s[col + 1];
                float2 r2;
                r2.x = o0 / (1.0f + __expf(-o0));
                r2.y = o1 / (1.0f + __expf(-o1));
                *(float2*)(op + col) = r2;
            }
        }
    }
}

// ---------------------------------------------------------------------------
extern "C" void kernel_launch(void* const* d_in, const int* in_sizes, int n_in,
                              void* d_out, int out_size) {
    const int*   tokens = (const int*)  d_in[0];
    const float* table  = (const float*)d_in[1];
    const float* pos    = (const float*)d_in[2];
    const float* ffn_w  = (const float*)d_in[3];
    const float* ffn_b  = (const float*)d_in[4];
    const float* ln_g   = (const float*)d_in[5];
    const float* ln_b   = (const float*)d_in[6];
    float* out = (float*)d_out;

    cudaFuncSetAttribute(gemm_ln_kernel, cudaFuncAttributeMaxDynamicSharedMemorySize, SM_GEMM);

    attn_kernel<<<NT / 32, 256>>>(tokens, table, pos);
    wconv_kernel<<<(E_ * E_) / 256, 256>>>(ffn_w);
    gemm_ln_kernel<<<NT / 64, 512, SM_GEMM>>>(ffn_b, ln_g, ln_b, out);
}

// round 8
// speedup vs baseline: 1.5904x; 1.5904x over previous
#include <cuda_runtime.h>
#include <cuda_fp16.h>
#include <cstdint>

#define B_  16
#define T_  2048
#define E_  512
#define H_  4
#define C_  3
#define NT  (B_ * T_)   // 32768 tokens

// ---------------------------------------------------------------------------
// Scratch (static device globals — allowed)
// ---------------------------------------------------------------------------
__device__ __half g_v[(size_t)NT * E_];    // 32 MB, fp16(v)
__device__ __half g_w[(size_t)E_ * E_];    // 512 KB, fp16(W)

__device__ __forceinline__ uint32_t smem_to_u32(const void* p) {
    uint32_t a;
    asm("{ .reg .u64 t; cvta.to.shared.u64 t, %1; cvt.u32.u64 %0, t; }" : "=r"(a) : "l"(p));
    return a;
}
__device__ __forceinline__ void cp16(uint32_t dst, const void* src) {
    asm volatile("cp.async.cg.shared.global [%0], [%1], 16;" :: "r"(dst), "l"(src));
}
__device__ __forceinline__ void ldm_x4(uint32_t* r, uint32_t addr) {
    asm volatile("ldmatrix.sync.aligned.m8n8.x4.shared.b16 {%0,%1,%2,%3}, [%4];"
                 : "=r"(r[0]), "=r"(r[1]), "=r"(r[2]), "=r"(r[3]) : "r"(addr));
}
__device__ __forceinline__ void mma_fp16(float* d, const uint32_t* a, const uint32_t* b) {
    asm volatile(
        "mma.sync.aligned.m16n8k16.row.col.f32.f16.f16.f32 "
        "{%0,%1,%2,%3}, {%4,%5,%6,%7}, {%8,%9}, {%0,%1,%2,%3};"
        : "+f"(d[0]), "+f"(d[1]), "+f"(d[2]), "+f"(d[3])
        : "r"(a[0]), "r"(a[1]), "r"(a[2]), "r"(a[3]), "r"(b[0]), "r"(b[1]));
}

// ---------------------------------------------------------------------------
// Kernel A: embed gather + windowed positional attention -> v (fp16)
// Multi-head collapse: out[e] = sum_c coeff[c]*x_c[e],
//   coeff[c] = dot(x_c, ps[c]) with ps[c][e] = (sum_h pos[h][e][c]) / 12.
// Per warp: 4 consecutive tokens, rolling window (reuse 2/3 rows).
// All gathers as float4, ps via conflict-free LDS.128.
// ---------------------------------------------------------------------------
__global__ __launch_bounds__(256) void attn_kernel(const int* __restrict__ tokens,
                                                   const float* __restrict__ table,
                                                   const float* __restrict__ pos) {
    __shared__ float ps[C_][E_];   // 6 KB
    int tid = threadIdx.x;
    for (int i = tid; i < E_ * C_; i += 256) {
        float v = pos[i] + pos[E_ * C_ + i] + pos[2 * E_ * C_ + i] + pos[3 * E_ * C_ + i];
        ps[i % 3][i / 3] = v * (1.0f / 12.0f);
    }
    __syncthreads();

    const float4* pc0 = (const float4*)ps[0];
    const float4* pc1 = (const float4*)ps[1];
    const float4* pc2 = (const float4*)ps[2];

    int warp = tid >> 5, lane = tid & 31;
    int base = blockIdx.x * 32 + warp * 4;
    int t0 = base & (T_ - 1);

    float4 x0[4], x1[4], x2[4];
    const float4 z4 = make_float4(0.f, 0.f, 0.f, 0.f);

    if (t0 >= 2) {
        const float4* rp = (const float4*)(table + (size_t)tokens[base - 2] * E_);
        #pragma unroll
        for (int j = 0; j < 4; ++j) x0[j] = rp[lane + j * 32];
    } else {
        #pragma unroll
        for (int j = 0; j < 4; ++j) x0[j] = z4;
    }
    if (t0 >= 1) {
        const float4* rp = (const float4*)(table + (size_t)tokens[base - 1] * E_);
        #pragma unroll
        for (int j = 0; j < 4; ++j) x1[j] = rp[lane + j * 32];
    } else {
        #pragma unroll
        for (int j = 0; j < 4; ++j) x1[j] = z4;
    }

    #pragma unroll
    for (int it = 0; it < 4; ++it) {
        int g = base + it;
        {
            const float4* rp = (const float4*)(table + (size_t)tokens[g] * E_);
            #pragma unroll
            for (int j = 0; j < 4; ++j) x2[j] = rp[lane + j * 32];
        }

        float s0 = 0.f, s1 = 0.f, s2 = 0.f;
        #pragma unroll
        for (int j = 0; j < 4; ++j) {
            float4 p0 = pc0[lane + j * 32];
            float4 p1 = pc1[lane + j * 32];
            float4 p2 = pc2[lane + j * 32];
            s0 += x0[j].x * p0.x + x0[j].y * p0.y + x0[j].z * p0.z + x0[j].w * p0.w;
            s1 += x1[j].x * p1.x + x1[j].y * p1.y + x1[j].z * p1.z + x1[j].w * p1.w;
            s2 += x2[j].x * p2.x + x2[j].y * p2.y + x2[j].z * p2.z + x2[j].w * p2.w;
        }
        #pragma unroll
        for (int off = 16; off > 0; off >>= 1) {
            s0 += __shfl_xor_sync(0xffffffffu, s0, off);
            s1 += __shfl_xor_sync(0xffffffffu, s1, off);
            s2 += __shfl_xor_sync(0xffffffffu, s2, off);
        }

        uint2* pv = (uint2*)(g_v + (size_t)g * E_);
        #pragma unroll
        for (int j = 0; j < 4; ++j) {
            float vx = s0 * x0[j].x + s1 * x1[j].x + s2 * x2[j].x;
            float vy = s0 * x0[j].y + s1 * x1[j].y + s2 * x2[j].y;
            float vz = s0 * x0[j].z + s1 * x1[j].z + s2 * x2[j].z;
            float vw = s0 * x0[j].w + s1 * x1[j].w + s2 * x2[j].w;
            __half2 h0 = __floats2half2_rn(vx, vy);
            __half2 h1 = __floats2half2_rn(vz, vw);
            uint2 u;
            u.x = *(uint32_t*)&h0;
            u.y = *(uint32_t*)&h1;
            pv[lane + j * 32] = u;
        }
        #pragma unroll
        for (int j = 0; j < 4; ++j) { x0[j] = x1[j]; x1[j] = x2[j]; }
    }
}

// ---------------------------------------------------------------------------
// Kernel W: convert ffn_w to fp16
// ---------------------------------------------------------------------------
__global__ __launch_bounds__(256) void wconv_kernel(const float* __restrict__ W) {
    int i = blockIdx.x * 256 + threadIdx.x;
    g_w[i] = __float2half_rn(W[i]);
}

// ---------------------------------------------------------------------------
// Kernel B: HMMA fp16 GEMM  Y = V @ W^T + bias  (proven R6 config)
// CTA tile 128x128, KBLK=32, 8 warps (warp tile 32x64), 4-stage cp.async.
// ---------------------------------------------------------------------------
#define KBLK   32
#define PITCH  80
#define TILE_B (128 * PITCH)            // 10240 bytes per operand tile
#define STAGE  (2 * TILE_B)             // A, B
#define NSTG   4
#define SM_GEMM (NSTG * STAGE)          // 81920 bytes

__global__ __launch_bounds__(256, 2) void gemm_kernel(const float* __restrict__ bias,
                                                      float* __restrict__ out) {
    extern __shared__ char smem[];
    const uint32_t sb = smem_to_u32(smem);

    const int tid  = threadIdx.x;
    const int wid  = tid >> 5, lane = tid & 31;
    const int wm   = wid >> 1;          // 0..3
    const int wn   = wid & 1;           // 0..1
    const int m0   = blockIdx.y * 128;
    const int n0   = blockIdx.x * 128;

    const char* va = (const char*)g_v;
    const char* wb = (const char*)g_w;

    auto issue_stage = [&](int kb) {
        const uint32_t st = sb + (kb & (NSTG - 1)) * STAGE;
        const int k0 = kb * KBLK;
        #pragma unroll
        for (int it = 0; it < 2; ++it) {
            int i = tid + it * 256;
            int r = i >> 2, c = i & 3;
            uint32_t so = r * PITCH + c * 16;
            size_t ga = ((size_t)(m0 + r) * E_ + k0 + c * 8) * 2;
            size_t gb = ((size_t)(n0 + r) * E_ + k0 + c * 8) * 2;
            cp16(st + 0 * TILE_B + so, va + ga);
            cp16(st + 1 * TILE_B + so, wb + gb);
        }
        asm volatile("cp.async.commit_group;" ::: "memory");
    };

    float d[2][8][4];
    #pragma unroll
    for (int i = 0; i < 2; ++i)
        #pragma unroll
        for (int j = 0; j < 8; ++j)
            #pragma unroll
            for (int q = 0; q < 4; ++q) d[i][j][q] = 0.0f;

    const int a_row = (lane & 7) + ((lane >> 3) & 1) * 8;
    const int a_k8  = (lane >> 4);
    const int b_row = (lane & 7) + ((lane >> 4) & 1) * 8;
    const int b_k8  = (lane >> 3) & 1;

    issue_stage(0);
    issue_stage(1);
    issue_stage(2);

    const int NKB = E_ / KBLK;   // 16
    for (int kb = 0; kb < NKB; ++kb) {
        if (kb < NKB - 2)
            asm volatile("cp.async.wait_group 2;" ::: "memory");
        else if (kb == NKB - 2)
            asm volatile("cp.async.wait_group 1;" ::: "memory");
        else
            asm volatile("cp.async.wait_group 0;" ::: "memory");
        __syncthreads();

        const uint32_t st = sb + (kb & (NSTG - 1)) * STAGE;
        const uint32_t aT = st + 0 * TILE_B;
        const uint32_t bT = st + 1 * TILE_B;

        #pragma unroll
        for (int kk = 0; kk < 2; ++kk) {
            uint32_t a[2][4];
            #pragma unroll
            for (int mi = 0; mi < 2; ++mi) {
                uint32_t off = (uint32_t)(wm * 32 + mi * 16 + a_row) * PITCH
                             + kk * 32 + a_k8 * 16;
                ldm_x4(a[mi], aT + off);
            }
            #pragma unroll
            for (int ni = 0; ni < 4; ++ni) {
                uint32_t off = (uint32_t)(wn * 64 + ni * 16 + b_row) * PITCH
                             + kk * 32 + b_k8 * 16;
                uint32_t bq[4];
                ldm_x4(bq, bT + off);
                #pragma unroll
                for (int mi = 0; mi < 2; ++mi) {
                    mma_fp16(d[mi][ni * 2 + 0], a[mi], bq + 0);
                    mma_fp16(d[mi][ni * 2 + 1], a[mi], bq + 2);
                }
            }
        }
        __syncthreads();
        if (kb + 3 < NKB) issue_stage(kb + 3);
    }

    // Epilogue: + bias, write out
    const int g = lane >> 2, t = lane & 3;
    #pragma unroll
    for (int mi = 0; mi < 2; ++mi) {
        #pragma unroll
        for (int ni = 0; ni < 4; ++ni) {
            #pragma unroll
            for (int h = 0; h < 2; ++h) {
                int col = n0 + wn * 64 + ni * 16 + h * 8 + t * 2;
                float b0 = __ldg(bias + col), b1 = __ldg(bias + col + 1);
                int row = m0 + wm * 32 + mi * 16 + g;
                float* o0 = out + (size_t)row * E_ + col;
                float* o1 = out + (size_t)(row + 8) * E_ + col;
                const float* dd = d[mi][ni * 2 + h];
                o0[0] = dd[0] + b0; o0[1] = dd[1] + b1;
                o1[0] = dd[2] + b0; o1[1] = dd[3] + b1;
            }
        }
    }
}

// ---------------------------------------------------------------------------
// Kernel C: in-place LayerNorm + swish, float4, 2 rows per 256-thread block
// ---------------------------------------------------------------------------
__global__ __launch_bounds__(256) void ln_kernel(const float* __restrict__ gamma,
                                                 const float* __restrict__ beta,
                                                 float* __restrict__ out) {
    int tid = threadIdx.x;
    int row = blockIdx.x * 2 + (tid >> 7);
    int tc  = (tid & 127) * 4;
    float* p = out + (size_t)row * E_ + tc;

    float4 y = *(const float4*)p;
    float sum = y.x + y.y + y.z + y.w;
    float sq  = y.x * y.x + y.y * y.y + y.z * y.z + y.w * y.w;

    #pragma unroll
    for (int off = 16; off > 0; off >>= 1) {
        sum += __shfl_xor_sync(0xffffffffu, sum, off);
        sq  += __shfl_xor_sync(0xffffffffu, sq,  off);
    }
    __shared__ float ssum[8], ssq[8];
    int warp = tid >> 5, lane = tid & 31;
    if (lane == 0) { ssum[warp] = sum; ssq[warp] = sq; }
    __syncthreads();
    int wbse = (tid >> 7) * 4;
    sum = ssum[wbse] + ssum[wbse + 1] + ssum[wbse + 2] + ssum[wbse + 3];
    sq  = ssq[wbse]  + ssq[wbse + 1]  + ssq[wbse + 2]  + ssq[wbse + 3];

    float mean = sum * (1.0f / E_);
    float var  = sq * (1.0f / E_) - mean * mean;
    float rstd = rsqrtf(var + 1e-5f);

    float4 gm = *(const float4*)(gamma + tc);
    float4 bt = *(const float4*)(beta + tc);
    float4 o;
    o.x = (y.x - mean) * rstd * gm.x + bt.x;
    o.y = (y.y - mean) * rstd * gm.y + bt.y;
    o.z = (y.z - mean) * rstd * gm.z + bt.z;
    o.w = (y.w - mean) * rstd * gm.w + bt.w;
    o.x = o.x / (1.0f + __expf(-o.x));
    o.y = o.y / (1.0f + __expf(-o.y));
    o.z = o.z / (1.0f + __expf(-o.z));
    o.w = o.w / (1.0f + __expf(-o.w));
    *(float4*)p = o;
}

// ---------------------------------------------------------------------------
extern "C" void kernel_launch(void* const* d_in, const int* in_sizes, int n_in,
                              void* d_out, int out_size) {
    const int*   tokens = (const int*)  d_in[0];
    const float* table  = (const float*)d_in[1];
    const float* pos    = (const float*)d_in[2];
    const float* ffn_w  = (const float*)d_in[3];
    const float* ffn_b  = (const float*)d_in[4];
    const float* ln_g   = (const float*)d_in[5];
    const float* ln_b   = (const float*)d_in[6];
    float* out = (float*)d_out;

    cudaFuncSetAttribute(gemm_kernel, cudaFuncAttributeMaxDynamicSharedMemorySize, SM_GEMM);

    attn_kernel<<<NT / 32, 256>>>(tokens, table, pos);
    wconv_kernel<<<(E_ * E_) / 256, 256>>>(ffn_w);
    dim3 gg(E_ / 128, NT / 128);   // (4, 256)
    gemm_kernel<<<gg, 256, SM_GEMM>>>(ffn_b, out);
    ln_kernel<<<NT / 2, 256>>>(ln_g, ln_b, out);
}

// round 9
// speedup vs baseline: 1.7900x; 1.1255x over previous
#include <cuda_runtime.h>
#include <cuda_fp16.h>
#include <cstdint>

#define B_  16
#define T_  2048
#define E_  512
#define H_  4
#define C_  3
#define NT  (B_ * T_)   // 32768 tokens

// ---------------------------------------------------------------------------
// Scratch (static device globals — allowed)
// ---------------------------------------------------------------------------
__device__ __half g_v[(size_t)NT * E_];    // 32 MB, fp16(v)
__device__ __half g_w[(size_t)E_ * E_];    // 512 KB, fp16(W)

__device__ __forceinline__ uint32_t smem_to_u32(const void* p) {
    uint32_t a;
    asm("{ .reg .u64 t; cvta.to.shared.u64 t, %1; cvt.u32.u64 %0, t; }" : "=r"(a) : "l"(p));
    return a;
}
__device__ __forceinline__ void cp16(uint32_t dst, const void* src) {
    asm volatile("cp.async.cg.shared.global [%0], [%1], 16;" :: "r"(dst), "l"(src));
}
__device__ __forceinline__ void ldm_x4(uint32_t* r, uint32_t addr) {
    asm volatile("ldmatrix.sync.aligned.m8n8.x4.shared.b16 {%0,%1,%2,%3}, [%4];"
                 : "=r"(r[0]), "=r"(r[1]), "=r"(r[2]), "=r"(r[3]) : "r"(addr));
}
__device__ __forceinline__ void mma_fp16(float* d, const uint32_t* a, const uint32_t* b) {
    asm volatile(
        "mma.sync.aligned.m16n8k16.row.col.f32.f16.f16.f32 "
        "{%0,%1,%2,%3}, {%4,%5,%6,%7}, {%8,%9}, {%0,%1,%2,%3};"
        : "+f"(d[0]), "+f"(d[1]), "+f"(d[2]), "+f"(d[3])
        : "r"(a[0]), "r"(a[1]), "r"(a[2]), "r"(a[3]), "r"(b[0]), "r"(b[1]));
}

// ---------------------------------------------------------------------------
// Kernel A: embed gather + windowed positional attention -> v (fp16)
// Multi-head collapse: out[e] = sum_c coeff[c]*x_c[e],
//   coeff[c] = dot(x_c, ps[c]) with ps[c][e] = (sum_h pos[h][e][c]) / 12.
// ---------------------------------------------------------------------------
__global__ __launch_bounds__(256) void attn_kernel(const int* __restrict__ tokens,
                                                   const float* __restrict__ table,
                                                   const float* __restrict__ pos) {
    __shared__ float ps[C_][E_];   // 6 KB
    int tid = threadIdx.x;
    for (int i = tid; i < E_ * C_; i += 256) {
        float v = pos[i] + pos[E_ * C_ + i] + pos[2 * E_ * C_ + i] + pos[3 * E_ * C_ + i];
        ps[i % 3][i / 3] = v * (1.0f / 12.0f);
    }
    __syncthreads();

    const float4* pc0 = (const float4*)ps[0];
    const float4* pc1 = (const float4*)ps[1];
    const float4* pc2 = (const float4*)ps[2];

    int warp = tid >> 5, lane = tid & 31;
    int base = blockIdx.x * 32 + warp * 4;
    int t0 = base & (T_ - 1);

    float4 x0[4], x1[4], x2[4];
    const float4 z4 = make_float4(0.f, 0.f, 0.f, 0.f);

    if (t0 >= 2) {
        const float4* rp = (const float4*)(table + (size_t)tokens[base - 2] * E_);
        #pragma unroll
        for (int j = 0; j < 4; ++j) x0[j] = rp[lane + j * 32];
    } else {
        #pragma unroll
        for (int j = 0; j < 4; ++j) x0[j] = z4;
    }
    if (t0 >= 1) {
        const float4* rp = (const float4*)(table + (size_t)tokens[base - 1] * E_);
        #pragma unroll
        for (int j = 0; j < 4; ++j) x1[j] = rp[lane + j * 32];
    } else {
        #pragma unroll
        for (int j = 0; j < 4; ++j) x1[j] = z4;
    }

    #pragma unroll
    for (int it = 0; it < 4; ++it) {
        int g = base + it;
        {
            const float4* rp = (const float4*)(table + (size_t)tokens[g] * E_);
            #pragma unroll
            for (int j = 0; j < 4; ++j) x2[j] = rp[lane + j * 32];
        }

        float s0 = 0.f, s1 = 0.f, s2 = 0.f;
        #pragma unroll
        for (int j = 0; j < 4; ++j) {
            float4 p0 = pc0[lane + j * 32];
            float4 p1 = pc1[lane + j * 32];
            float4 p2 = pc2[lane + j * 32];
            s0 += x0[j].x * p0.x + x0[j].y * p0.y + x0[j].z * p0.z + x0[j].w * p0.w;
            s1 += x1[j].x * p1.x + x1[j].y * p1.y + x1[j].z * p1.z + x1[j].w * p1.w;
            s2 += x2[j].x * p2.x + x2[j].y * p2.y + x2[j].z * p2.z + x2[j].w * p2.w;
        }
        #pragma unroll
        for (int off = 16; off > 0; off >>= 1) {
            s0 += __shfl_xor_sync(0xffffffffu, s0, off);
            s1 += __shfl_xor_sync(0xffffffffu, s1, off);
            s2 += __shfl_xor_sync(0xffffffffu, s2, off);
        }

        uint2* pv = (uint2*)(g_v + (size_t)g * E_);
        #pragma unroll
        for (int j = 0; j < 4; ++j) {
            float vx = s0 * x0[j].x + s1 * x1[j].x + s2 * x2[j].x;
            float vy = s0 * x0[j].y + s1 * x1[j].y + s2 * x2[j].y;
            float vz = s0 * x0[j].z + s1 * x1[j].z + s2 * x2[j].z;
            float vw = s0 * x0[j].w + s1 * x1[j].w + s2 * x2[j].w;
            __half2 h0 = __floats2half2_rn(vx, vy);
            __half2 h1 = __floats2half2_rn(vz, vw);
            uint2 u;
            u.x = *(uint32_t*)&h0;
            u.y = *(uint32_t*)&h1;
            pv[lane + j * 32] = u;
        }
        #pragma unroll
        for (int j = 0; j < 4; ++j) { x0[j] = x1[j]; x1[j] = x2[j]; }
    }
}

// ---------------------------------------------------------------------------
// Kernel W: convert ffn_w to fp16
// ---------------------------------------------------------------------------
__global__ __launch_bounds__(256) void wconv_kernel(const float* __restrict__ W) {
    int i = blockIdx.x * 256 + threadIdx.x;
    g_w[i] = __float2half_rn(W[i]);
}

// ---------------------------------------------------------------------------
// Kernel B: HMMA fp16 GEMM  Y = V @ W^T + bias
// CTA tile 128x128, KBLK=64, 8 warps (warp tile 32x64), 3-stage cp.async.
// PITCH=144 (128B data + 16B pad) -> all ldmatrix phases conflict-free.
// ---------------------------------------------------------------------------
#define KBLK   64
#define PITCH  144
#define TILE_B (128 * PITCH)            // 18432 bytes per operand tile
#define STAGE  (2 * TILE_B)             // A, B = 36864
#define NSTG   3
#define SM_GEMM (NSTG * STAGE)          // 110592 bytes

__global__ __launch_bounds__(256, 2) void gemm_kernel(const float* __restrict__ bias,
                                                      float* __restrict__ out) {
    extern __shared__ char smem[];
    const uint32_t sb = smem_to_u32(smem);

    const int tid  = threadIdx.x;
    const int wid  = tid >> 5, lane = tid & 31;
    const int wm   = wid >> 1;          // 0..3
    const int wn   = wid & 1;           // 0..1
    const int m0   = blockIdx.y * 128;
    const int n0   = blockIdx.x * 128;

    const char* va = (const char*)g_v;
    const char* wb = (const char*)g_w;

    auto issue_stage = [&](int kb) {
        const uint32_t st = sb + (kb % NSTG) * STAGE;
        const int k0 = kb * KBLK;
        #pragma unroll
        for (int it = 0; it < 4; ++it) {
            int i = tid + it * 256;            // 0..1023
            int r = i >> 3, c = i & 7;
            uint32_t so = r * PITCH + c * 16;
            size_t ga = ((size_t)(m0 + r) * E_ + k0 + c * 8) * 2;
            size_t gb = ((size_t)(n0 + r) * E_ + k0 + c * 8) * 2;
            cp16(st + 0 * TILE_B + so, va + ga);
            cp16(st + 1 * TILE_B + so, wb + gb);
        }
        asm volatile("cp.async.commit_group;" ::: "memory");
    };

    float d[2][8][4];
    #pragma unroll
    for (int i = 0; i < 2; ++i)
        #pragma unroll
        for (int j = 0; j < 8; ++j)
            #pragma unroll
            for (int q = 0; q < 4; ++q) d[i][j][q] = 0.0f;

    const int a_row = (lane & 7) + ((lane >> 3) & 1) * 8;
    const int a_k8  = (lane >> 4);
    const int b_row = (lane & 7) + ((lane >> 4) & 1) * 8;
    const int b_k8  = (lane >> 3) & 1;

    issue_stage(0);
    issue_stage(1);

    const int NKB = E_ / KBLK;   // 8
    for (int kb = 0; kb < NKB; ++kb) {
        if (kb < NKB - 1)
            asm volatile("cp.async.wait_group 1;" ::: "memory");
        else
            asm volatile("cp.async.wait_group 0;" ::: "memory");
        __syncthreads();

        // safe: buffer (kb+2)%3 == (kb-1)%3, all its readers passed the barrier
        if (kb + 2 < NKB) issue_stage(kb + 2);

        const uint32_t st = sb + (kb % NSTG) * STAGE;
        const uint32_t aT = st + 0 * TILE_B;
        const uint32_t bT = st + 1 * TILE_B;

        #pragma unroll
        for (int kk = 0; kk < 4; ++kk) {
            uint32_t a[2][4];
            #pragma unroll
            for (int mi = 0; mi < 2; ++mi) {
                uint32_t off = (uint32_t)(wm * 32 + mi * 16 + a_row) * PITCH
                             + kk * 32 + a_k8 * 16;
                ldm_x4(a[mi], aT + off);
            }
            #pragma unroll
            for (int ni = 0; ni < 4; ++ni) {
                uint32_t off = (uint32_t)(wn * 64 + ni * 16 + b_row) * PITCH
                             + kk * 32 + b_k8 * 16;
                uint32_t bq[4];
                ldm_x4(bq, bT + off);
                #pragma unroll
                for (int mi = 0; mi < 2; ++mi) {
                    mma_fp16(d[mi][ni * 2 + 0], a[mi], bq + 0);
                    mma_fp16(d[mi][ni * 2 + 1], a[mi], bq + 2);
                }
            }
        }
    }

    // Epilogue: + bias, write out
    const int g = lane >> 2, t = lane & 3;
    #pragma unroll
    for (int mi = 0; mi < 2; ++mi) {
        #pragma unroll
        for (int ni = 0; ni < 4; ++ni) {
            #pragma unroll
            for (int h = 0; h < 2; ++h) {
                int col = n0 + wn * 64 + ni * 16 + h * 8 + t * 2;
                float b0 = __ldg(bias + col), b1 = __ldg(bias + col + 1);
                int row = m0 + wm * 32 + mi * 16 + g;
                float* o0 = out + (size_t)row * E_ + col;
                float* o1 = out + (size_t)(row + 8) * E_ + col;
                const float* dd = d[mi][ni * 2 + h];
                o0[0] = dd[0] + b0; o0[1] = dd[1] + b1;
                o1[0] = dd[2] + b0; o1[1] = dd[3] + b1;
            }
        }
    }
}

// ---------------------------------------------------------------------------
// Kernel C: in-place LayerNorm + swish — warp per row, no block reduction.
// 256 threads = 8 warps = 8 rows per block; each lane owns 16 elements.
// ---------------------------------------------------------------------------
__global__ __launch_bounds__(256) void ln_kernel(const float* __restrict__ gamma,
                                                 const float* __restrict__ beta,
                                                 float* __restrict__ out) {
    int tid = threadIdx.x;
    int warp = tid >> 5, lane = tid & 31;
    int row = blockIdx.x * 8 + warp;
    float4* p = (float4*)(out + (size_t)row * E_);

    float4 y[4];
    #pragma unroll
    for (int j = 0; j < 4; ++j) y[j] = p[lane + j * 32];

    float sum = 0.f, sq = 0.f;
    #pragma unroll
    for (int j = 0; j < 4; ++j) {
        sum += y[j].x + y[j].y + y[j].z + y[j].w;
        sq  += y[j].x * y[j].x + y[j].y * y[j].y + y[j].z * y[j].z + y[j].w * y[j].w;
    }
    #pragma unroll
    for (int off = 16; off > 0; off >>= 1) {
        sum += __shfl_xor_sync(0xffffffffu, sum, off);
        sq  += __shfl_xor_sync(0xffffffffu, sq,  off);
    }

    float mean = sum * (1.0f / E_);
    float var  = sq * (1.0f / E_) - mean * mean;
    float rstd = rsqrtf(var + 1e-5f);

    const float4* gmp = (const float4*)gamma;
    const float4* btp = (const float4*)beta;
    #pragma unroll
    for (int j = 0; j < 4; ++j) {
        float4 gm = gmp[lane + j * 32];
        float4 bt = btp[lane + j * 32];
        float4 o;
        o.x = (y[j].x - mean) * rstd * gm.x + bt.x;
        o.y = (y[j].y - mean) * rstd * gm.y + bt.y;
        o.z = (y[j].z - mean) * rstd * gm.z + bt.z;
        o.w = (y[j].w - mean) * rstd * gm.w + bt.w;
        o.x = o.x / (1.0f + __expf(-o.x));
        o.y = o.y / (1.0f + __expf(-o.y));
        o.z = o.z / (1.0f + __expf(-o.z));
        o.w = o.w / (1.0f + __expf(-o.w));
        p[lane + j * 32] = o;
    }
}

// ---------------------------------------------------------------------------
extern "C" void kernel_launch(void* const* d_in, const int* in_sizes, int n_in,
                              void* d_out, int out_size) {
    const int*   tokens = (const int*)  d_in[0];
    const float* table  = (const float*)d_in[1];
    const float* pos    = (const float*)d_in[2];
    const float* ffn_w  = (const float*)d_in[3];
    const float* ffn_b  = (const float*)d_in[4];
    const float* ln_g   = (const float*)d_in[5];
    const float* ln_b   = (const float*)d_in[6];
    float* out = (float*)d_out;

    cudaFuncSetAttribute(gemm_kernel, cudaFuncAttributeMaxDynamicSharedMemorySize, SM_GEMM);

    attn_kernel<<<NT / 32, 256>>>(tokens, table, pos);
    wconv_kernel<<<(E_ * E_) / 256, 256>>>(ffn_w);
    dim3 gg(E_ / 128, NT / 128);   // (4, 256)
    gemm_kernel<<<gg, 256, SM_GEMM>>>(ffn_b, out);
    ln_kernel<<<NT / 8, 256>>>(ln_g, ln_b, out);
}